// round 4
// baseline (speedup 1.0000x reference)
#include <cuda_runtime.h>
#include <cstdint>

#define B_    64
#define S_    2048
#define H_    1024
#define SPLIT 32
#define CHUNK (S_ / SPLIT)        // 64 timesteps per CTA
#define TILE  8
#define NTILES (CHUNK / TILE)     // 8
#define STAGES 3
#define THREADS 256               // one float4 column slice per thread
#define WARPS (THREADS / 32)

// Scratch (allocation-free: __device__ globals)
__device__ float g_expE [B_ * S_];             // exp(tanh(score)) per (b,s)
__device__ float g_partL[B_ * SPLIT];          // partial sum of exp per chunk
__device__ float g_partC[B_ * SPLIT * H_];     // partial context per chunk (8 MiB)
__device__ float g_linv [B_];                  // 1 / sum_exp per batch

__device__ __forceinline__ void cp16(uint32_t dst_smem, const float* src) {
    asm volatile("cp.async.cg.shared.global [%0], [%1], 16;\n"
                 :: "r"(dst_smem), "l"(src));
}
#define CP_COMMIT() asm volatile("cp.async.commit_group;\n" ::: "memory")
#define CP_WAIT1()  asm volatile("cp.async.wait_group 1;\n" ::: "memory")
#define CP_WAIT0()  asm volatile("cp.async.wait_group 0;\n" ::: "memory")

// ---------------------------------------------------------------------------
// Pass 1: single DRAM read of rnn_output via a 3-stage cp.async pipeline.
// Thread t owns H columns [4t,4t+4) and copies exactly those bytes of each
// row -> stage readiness is per-thread (wait_group), NO barrier needed for
// data. Barriers only order the tiny dot-reduce smem (ping-pong buffers).
// tanh in [-1,1] -> softmax needs no max subtraction.
// ---------------------------------------------------------------------------
__global__ __launch_bounds__(THREADS)
void pass1_kernel(const float* __restrict__ x,
                  const float* __restrict__ w,
                  const float* __restrict__ bptr)
{
    extern __shared__ float xs[];                  // [STAGES][TILE][H_] 96 KB
    __shared__ float red[2][WARPS * TILE];         // ping-pong partial dots
    __shared__ float tt[2][TILE];                  // ping-pong broadcast t
    __shared__ float lred[TILE];

    const int b     = blockIdx.x / SPLIT;
    const int chunk = blockIdx.x % SPLIT;
    const int tid   = threadIdx.x;
    const int warp  = tid >> 5;
    const int lane  = tid & 31;
    const float bias = __ldg(bptr);

    const float4 w4 = reinterpret_cast<const float4*>(w)[tid];

    float4 acc = make_float4(0.f, 0.f, 0.f, 0.f);
    float lsum = 0.f;                              // only tid%8==0 accumulates

    const int s0 = chunk * CHUNK;
    const float* xrow0 = x + ((size_t)b * S_ + s0) * H_ + 4 * tid;

    uint32_t xs_base;
    {
        uint64_t g = __cvta_generic_to_shared(xs);
        xs_base = (uint32_t)g + (uint32_t)(16 * tid);   // this thread's column
    }
    const uint32_t stage_bytes = TILE * H_ * 4;         // 32 KB
    const uint32_t row_bytes   = H_ * 4;

    // prologue: fill STAGES-1 stages
    #pragma unroll
    for (int t = 0; t < STAGES - 1; t++) {
        const float* src = xrow0 + (size_t)(t * TILE) * H_;
        #pragma unroll
        for (int s = 0; s < TILE; s++)
            cp16(xs_base + t * stage_bytes + s * row_bytes,
                 src + (size_t)s * H_);
        CP_COMMIT();
    }

    #pragma unroll 1
    for (int tile = 0; tile < NTILES; tile++) {
        if (tile < NTILES - (STAGES - 1)) { CP_WAIT1(); } else { CP_WAIT0(); }

        const int stg = tile % STAGES;
        const int p   = tile & 1;
        const uint32_t sb_off = (uint32_t)stg * stage_bytes;

        // read own column of 8 rows from smem (self-written via cp.async)
        float4 xr[TILE];
        #pragma unroll
        for (int s = 0; s < TILE; s++)
            xr[s] = *reinterpret_cast<const float4*>(
                reinterpret_cast<const char*>(xs)
                + (sb_off + s * row_bytes) + 16 * tid);

        float d[TILE];
        #pragma unroll
        for (int s = 0; s < TILE; s++)
            d[s] = xr[s].x * w4.x + xr[s].y * w4.y
                 + xr[s].z * w4.z + xr[s].w * w4.w;

        #pragma unroll
        for (int s = 0; s < TILE; s++) {
            #pragma unroll
            for (int off = 16; off; off >>= 1)
                d[s] += __shfl_xor_sync(0xffffffffu, d[s], off);
        }
        if (lane == 0) {
            #pragma unroll
            for (int s = 0; s < TILE; s++)
                red[p][warp * TILE + s] = d[s];
        }
        __syncthreads();

        if (tid < 64) {
            const int s = tid >> 3;
            const int j = tid & 7;
            float v = red[p][j * TILE + s];
            v += __shfl_xor_sync(0xffffffffu, v, 4);
            v += __shfl_xor_sync(0xffffffffu, v, 2);
            v += __shfl_xor_sync(0xffffffffu, v, 1);
            if (j == 0) {
                const float t = __expf(tanhf(v + bias));
                tt[p][s] = t;
                g_expE[(size_t)b * S_ + s0 + tile * TILE + s] = t;
                lsum += t;
            }
        }
        __syncthreads();

        // Phase B from registers
        #pragma unroll
        for (int s = 0; s < TILE; s++) {
            const float t = tt[p][s];
            acc.x += t * xr[s].x;
            acc.y += t * xr[s].y;
            acc.z += t * xr[s].z;
            acc.w += t * xr[s].w;
        }

        // issue next stage's copies (keeps DRAM busy through next barriers)
        const int nt = tile + STAGES - 1;
        if (nt < NTILES) {
            const float* src = xrow0 + (size_t)(nt * TILE) * H_;
            const uint32_t doff = (uint32_t)(nt % STAGES) * stage_bytes;
            #pragma unroll
            for (int s = 0; s < TILE; s++)
                cp16(xs_base + doff + s * row_bytes, src + (size_t)s * H_);
            CP_COMMIT();
        }
    }

    reinterpret_cast<float4*>(
        g_partC + ((size_t)b * SPLIT + chunk) * H_)[tid] = acc;

    if (tid < 64 && (tid & 7) == 0) lred[tid >> 3] = lsum;
    __syncthreads();
    if (tid == 0) {
        float l = 0.f;
        #pragma unroll
        for (int i = 0; i < TILE; i++) l += lred[i];
        g_partL[b * SPLIT + chunk] = l;
    }
}

// ---------------------------------------------------------------------------
// Pass 2: per-batch combine of SPLIT partials -> context [B,H] and 1/l.
// ---------------------------------------------------------------------------
__global__ __launch_bounds__(THREADS)
void pass2_kernel(float* __restrict__ ctx_out)
{
    const int b   = blockIdx.x;
    const int tid = threadIdx.x;
    __shared__ float s_inv;

    if (tid < 32) {
        float l = 0.f;
        for (int c = tid; c < SPLIT; c += 32)
            l += g_partL[b * SPLIT + c];
        #pragma unroll
        for (int off = 16; off; off >>= 1)
            l += __shfl_xor_sync(0xffffffffu, l, off);
        if (tid == 0) {
            float inv = 1.f / l;
            s_inv = inv;
            g_linv[b] = inv;
        }
    }
    __syncthreads();
    const float inv = s_inv;

    float4 acc = make_float4(0.f, 0.f, 0.f, 0.f);
    #pragma unroll
    for (int c = 0; c < SPLIT; c++) {
        float4 v = reinterpret_cast<const float4*>(
            g_partC + ((size_t)b * SPLIT + c) * H_)[tid];
        acc.x += v.x; acc.y += v.y; acc.z += v.z; acc.w += v.w;
    }
    acc.x *= inv; acc.y *= inv; acc.z *= inv; acc.w *= inv;
    reinterpret_cast<float4*>(ctx_out + (size_t)b * H_)[tid] = acc;
}

// ---------------------------------------------------------------------------
// Pass 3: weights[b,s] = expE[b,s] / l[b]   (float4: S_ % 4 == 0)
// ---------------------------------------------------------------------------
__global__ __launch_bounds__(THREADS)
void pass3_kernel(float* __restrict__ w_out)
{
    const int i = blockIdx.x * THREADS + threadIdx.x;  // over B_*S_/4
    if (i < B_ * S_ / 4) {
        const int b = i / (S_ / 4);
        const float inv = g_linv[b];
        float4 e = reinterpret_cast<const float4*>(g_expE)[i];
        e.x *= inv; e.y *= inv; e.z *= inv; e.w *= inv;
        reinterpret_cast<float4*>(w_out)[i] = e;
    }
}

extern "C" void kernel_launch(void* const* d_in, const int* in_sizes, int n_in,
                              void* d_out, int out_size)
{
    const float* x    = (const float*)d_in[0];   // rnn_output [B,S,H]
    const float* w    = (const float*)d_in[1];   // attn_w [H]
    const float* bptr = (const float*)d_in[2];   // attn_b scalar

    float* out = (float*)d_out;                  // context [B,H] then weights [B,S]
    float* ctx_out = out;
    float* wts_out = out + (size_t)B_ * H_;

    const int dyn_smem = STAGES * TILE * H_ * 4; // 96 KB
    cudaFuncSetAttribute(pass1_kernel,
                         cudaFuncAttributeMaxDynamicSharedMemorySize, dyn_smem);

    pass1_kernel<<<B_ * SPLIT, THREADS, dyn_smem>>>(x, w, bptr);
    pass2_kernel<<<B_, THREADS>>>(ctx_out);
    pass3_kernel<<<(B_ * S_ / 4 + THREADS - 1) / THREADS, THREADS>>>(wts_out);
}

// round 5
// speedup vs baseline: 1.0287x; 1.0287x over previous
#include <cuda_runtime.h>
#include <cstdint>

#define B_    64
#define S_    2048
#define H_    1024
#define TILE  8
#define TPB   (S_ / TILE)          // 256 tiles per batch (power of 2)
#define NTILES_TOTAL (B_ * TPB)    // 16384
#define GRID  592                  // 148 SMs * 4 CTAs/SM, all resident
#define NSLOTS (GRID * 2)          // <=2 flushes per CTA (span < TPB)
#define THREADS 256                // one float4 column slice per thread
#define WARPS (THREADS / 32)

// Scratch (allocation-free: __device__ globals)
__device__ float g_expE [B_ * S_];            // exp(tanh(score)) per row
__device__ float g_partC[NSLOTS * H_];        // tagged context partials (4.6 MiB)
__device__ float g_partL[NSLOTS];             // tagged lsum partials
__device__ int   g_tag  [NSLOTS];             // batch tag per slot (-1 = unused)
__device__ float g_linv [B_];                 // 1 / sum_exp per batch

// ---------------------------------------------------------------------------
// Pass 1 (persistent): single DRAM read of rnn_output.
// Thread t owns H columns [4t,4t+4). Work unit = tile of 8 consecutive rows
// (same batch). Per tile: front-batched float4 loads (MLP=8), partial dots,
// 2-barrier ping-pong block reduce, t=exp(tanh(.)) (tanh in [-1,1] -> no max
// subtraction), then acc += t*xr from registers. Contiguous 28/27-tile spans
// per CTA eliminate the wave tail; batch-boundary crossings flush to tagged
// slots (no atomics -> deterministic).
// ---------------------------------------------------------------------------
__global__ __launch_bounds__(THREADS, 4)
void pass1_kernel(const float* __restrict__ x,
                  const float* __restrict__ w,
                  const float* __restrict__ bptr)
{
    __shared__ float red[2][WARPS * TILE];   // ping-pong partial dots
    __shared__ float tt[2][TILE];            // ping-pong broadcast t
    __shared__ float lred[TILE];

    const int tid  = threadIdx.x;
    const int warp = tid >> 5;
    const int lane = tid & 31;
    const float bias = __ldg(bptr);
    const float4 w4 = reinterpret_cast<const float4*>(w)[tid];

    // balanced contiguous split: first R CTAs get Q+1 tiles, rest Q
    const int Q = NTILES_TOTAL / GRID;              // 27
    const int R = NTILES_TOTAL - Q * GRID;          // 400
    const int k = blockIdx.x;
    const int t0 = (k < R) ? k * (Q + 1) : R * (Q + 1) + (k - R) * Q;
    const int t1 = t0 + ((k < R) ? (Q + 1) : Q);

    float4 acc = make_float4(0.f, 0.f, 0.f, 0.f);
    float lsum = 0.f;                               // only tid%8==0 accumulates
    int cur_b = t0 / TPB;
    int slot  = k * 2;

    #pragma unroll 1
    for (int tile = t0; tile < t1; tile++) {
        const int b = tile / TPB;                   // TPB=256: becomes shift
        if (b != cur_b) {
            // flush partial for cur_b
            reinterpret_cast<float4*>(g_partC + (size_t)slot * H_)[tid] = acc;
            if (tid < 64 && (tid & 7) == 0) lred[tid >> 3] = lsum;
            __syncthreads();
            if (tid == 0) {
                float l = 0.f;
                #pragma unroll
                for (int i = 0; i < TILE; i++) l += lred[i];
                g_partL[slot] = l;
                g_tag[slot]   = cur_b;
            }
            __syncthreads();
            slot++;
            acc = make_float4(0.f, 0.f, 0.f, 0.f);
            lsum = 0.f;
            cur_b = b;
        }

        const size_t row0 = (size_t)tile * TILE;    // global row index
        const float4* xp = reinterpret_cast<const float4*>(x) +
                           row0 * (H_ / 4) + tid;

        // Phase A: front-batched loads (MLP=8), partial dots
        float4 xr[TILE];
        #pragma unroll
        for (int s = 0; s < TILE; s++)
            xr[s] = xp[(size_t)s * (H_ / 4)];

        float d[TILE];
        #pragma unroll
        for (int s = 0; s < TILE; s++)
            d[s] = xr[s].x * w4.x + xr[s].y * w4.y
                 + xr[s].z * w4.z + xr[s].w * w4.w;

        #pragma unroll
        for (int s = 0; s < TILE; s++) {
            #pragma unroll
            for (int off = 16; off; off >>= 1)
                d[s] += __shfl_xor_sync(0xffffffffu, d[s], off);
        }

        const int p = tile & 1;
        if (lane == 0) {
            #pragma unroll
            for (int s = 0; s < TILE; s++)
                red[p][warp * TILE + s] = d[s];
        }
        __syncthreads();

        if (tid < 64) {
            const int s = tid >> 3;
            const int j = tid & 7;
            float v = red[p][j * TILE + s];
            v += __shfl_xor_sync(0xffffffffu, v, 4);
            v += __shfl_xor_sync(0xffffffffu, v, 2);
            v += __shfl_xor_sync(0xffffffffu, v, 1);
            if (j == 0) {
                const float t = __expf(tanhf(v + bias));
                tt[p][s] = t;
                g_expE[row0 + s] = t;
                lsum += t;
            }
        }
        __syncthreads();

        // Phase B: consume xr[] from registers
        #pragma unroll
        for (int s = 0; s < TILE; s++) {
            const float t = tt[p][s];
            acc.x += t * xr[s].x;
            acc.y += t * xr[s].y;
            acc.z += t * xr[s].z;
            acc.w += t * xr[s].w;
        }
    }

    // final flush
    reinterpret_cast<float4*>(g_partC + (size_t)slot * H_)[tid] = acc;
    if (tid < 64 && (tid & 7) == 0) lred[tid >> 3] = lsum;
    __syncthreads();
    if (tid == 0) {
        float l = 0.f;
        #pragma unroll
        for (int i = 0; i < TILE; i++) l += lred[i];
        g_partL[slot] = l;
        g_tag[slot]   = cur_b;
        // mark any unused slot (deterministic every launch)
        if (slot == k * 2) g_tag[k * 2 + 1] = -1;
    }
}

// ---------------------------------------------------------------------------
// Pass 2: per-batch gather of tagged partials -> context [B,H] and 1/l.
// ---------------------------------------------------------------------------
__global__ __launch_bounds__(THREADS)
void pass2_kernel(float* __restrict__ ctx_out)
{
    const int b   = blockIdx.x;
    const int tid = threadIdx.x;
    __shared__ float s_inv;
    __shared__ int   s_match[NSLOTS / 32 + 32];  // compacted matching slots
    __shared__ int   s_nm;

    // warp 0 compacts matching slots + reduces lsum
    if (tid == 0) s_nm = 0;
    __syncthreads();
    if (tid < 32) {
        float l = 0.f;
        for (int s = tid; s < NSLOTS; s += 32) {
            if (g_tag[s] == b) {
                l += g_partL[s];
                int idx = atomicAdd(&s_nm, 1);
                s_match[idx] = s;
            }
        }
        #pragma unroll
        for (int off = 16; off; off >>= 1)
            l += __shfl_xor_sync(0xffffffffu, l, off);
        if (tid == 0) {
            float inv = 1.f / l;
            s_inv = inv;
            g_linv[b] = inv;
        }
    }
    __syncthreads();
    const float inv = s_inv;
    const int   nm  = s_nm;

    float4 acc = make_float4(0.f, 0.f, 0.f, 0.f);
    for (int i = 0; i < nm; i++) {
        const int s = s_match[i];
        float4 v = reinterpret_cast<const float4*>(
            g_partC + (size_t)s * H_)[tid];
        acc.x += v.x; acc.y += v.y; acc.z += v.z; acc.w += v.w;
    }
    acc.x *= inv; acc.y *= inv; acc.z *= inv; acc.w *= inv;
    reinterpret_cast<float4*>(ctx_out + (size_t)b * H_)[tid] = acc;
}

// ---------------------------------------------------------------------------
// Pass 3: weights[b,s] = expE[b,s] / l[b]   (float4: S_ % 4 == 0)
// ---------------------------------------------------------------------------
__global__ __launch_bounds__(THREADS)
void pass3_kernel(float* __restrict__ w_out)
{
    const int i = blockIdx.x * THREADS + threadIdx.x;  // over B_*S_/4
    if (i < B_ * S_ / 4) {
        const int b = i / (S_ / 4);
        const float inv = g_linv[b];
        float4 e = reinterpret_cast<const float4*>(g_expE)[i];
        e.x *= inv; e.y *= inv; e.z *= inv; e.w *= inv;
        reinterpret_cast<float4*>(w_out)[i] = e;
    }
}

extern "C" void kernel_launch(void* const* d_in, const int* in_sizes, int n_in,
                              void* d_out, int out_size)
{
    const float* x    = (const float*)d_in[0];   // rnn_output [B,S,H]
    const float* w    = (const float*)d_in[1];   // attn_w [H]
    const float* bptr = (const float*)d_in[2];   // attn_b scalar

    float* out = (float*)d_out;                  // context [B,H] then weights [B,S]
    float* ctx_out = out;
    float* wts_out = out + (size_t)B_ * H_;

    pass1_kernel<<<GRID, THREADS>>>(x, w, bptr);
    pass2_kernel<<<B_, THREADS>>>(ctx_out);
    pass3_kernel<<<(B_ * S_ / 4 + THREADS - 1) / THREADS, THREADS>>>(wts_out);
}

// round 6
// speedup vs baseline: 1.1166x; 1.0855x over previous
#include <cuda_runtime.h>
#include <cstdint>

#define B_    64
#define S_    2048
#define H_    1024
#define SPLIT 16
#define CHUNK (S_ / SPLIT)      // 128 timesteps per CTA
#define TILE  8
#define NTILES (CHUNK / TILE)   // 16
#define THREADS 256             // one float4 column slice per thread
#define WARPS (THREADS / 32)

// Scratch (allocation-free: __device__ globals)
__device__ float g_expE [B_ * S_];             // exp(tanh(score)) per (b,s)
__device__ float g_partL[B_ * SPLIT];          // partial sum of exp per chunk
__device__ float g_partC[B_ * SPLIT * H_];     // partial context per chunk (4 MiB)

// ---------------------------------------------------------------------------
// Pass 1: single DRAM read of rnn_output.
// Thread t owns H columns [4t,4t+4). Per tile of 8 timesteps:
//   1. front-batched float4 loads (MLP=8)  2. partial dots vs w4 (registers)
//   3. full warp-reduce of the 8 dots (lane 0)  4. lane0 writes 8 floats to
//      ping-pong red[p]  5. ONE __syncthreads  6. every warp redundantly
//      finishes: lanes 0-7 sum the 8 per-warp values (LDS), t=exp(tanh(.)),
//      broadcast via shuffle  7. acc += t*xr from registers.
// Ping-pong red[] makes a single barrier per tile legal. tanh in [-1,1] ->
// softmax needs no max subtraction. Redundant tanh/exp across warps is free
// (MUFU idle); removes the 2-warp serialized reduce + second barrier.
// ---------------------------------------------------------------------------
__global__ __launch_bounds__(THREADS, 4)
void pass1_kernel(const float* __restrict__ x,
                  const float* __restrict__ w,
                  const float* __restrict__ bptr)
{
    __shared__ float red[2][WARPS * TILE];   // ping-pong per-warp dot partials
    __shared__ float lred[TILE];

    const int b     = blockIdx.x / SPLIT;
    const int chunk = blockIdx.x % SPLIT;
    const int tid   = threadIdx.x;
    const int warp  = tid >> 5;
    const int lane  = tid & 31;
    const float bias = __ldg(bptr);
    const float4 w4 = reinterpret_cast<const float4*>(w)[tid];

    float4 acc = make_float4(0.f, 0.f, 0.f, 0.f);
    float lsum = 0.f;                        // warp 0, lanes 0-7 accumulate

    const int s0 = chunk * CHUNK;
    const float4* xp0 = reinterpret_cast<const float4*>(x) +
                        ((size_t)b * S_ + s0) * (H_ / 4) + tid;

    #pragma unroll 1
    for (int tile = 0; tile < NTILES; tile++) {
        const float4* xp = xp0 + (size_t)tile * TILE * (H_ / 4);
        const int p = tile & 1;

        // 1. front-batched loads
        float4 xr[TILE];
        #pragma unroll
        for (int s = 0; s < TILE; s++)
            xr[s] = xp[(size_t)s * (H_ / 4)];

        // 2. partial dots
        float d[TILE];
        #pragma unroll
        for (int s = 0; s < TILE; s++)
            d[s] = xr[s].x * w4.x + xr[s].y * w4.y
                 + xr[s].z * w4.z + xr[s].w * w4.w;

        // 3. full warp reduce (lane 0 holds result)
        #pragma unroll
        for (int s = 0; s < TILE; s++) {
            #pragma unroll
            for (int off = 16; off; off >>= 1)
                d[s] += __shfl_xor_sync(0xffffffffu, d[s], off);
        }

        // 4. lane 0 publishes 8 per-warp partials
        if (lane == 0) {
            #pragma unroll
            for (int s = 0; s < TILE; s++)
                red[p][warp * TILE + s] = d[s];
        }

        // 5. single barrier per tile (ping-pong makes this sufficient)
        __syncthreads();

        // 6. redundant finish in every warp: lanes 0-7 own one timestep each
        float t = 0.f;
        if (lane < TILE) {
            float v = 0.f;
            #pragma unroll
            for (int j = 0; j < WARPS; j++)
                v += red[p][j * TILE + lane];
            t = __expf(tanhf(v + bias));
            if (warp == 0) {
                g_expE[(size_t)b * S_ + s0 + tile * TILE + lane] = t;
                lsum += t;
            }
        }

        // 7. broadcast t and accumulate from registers
        #pragma unroll
        for (int s = 0; s < TILE; s++) {
            const float ts = __shfl_sync(0xffffffffu, t, s);
            acc.x += ts * xr[s].x;
            acc.y += ts * xr[s].y;
            acc.z += ts * xr[s].z;
            acc.w += ts * xr[s].w;
        }
    }

    // write partial context (each thread owns its own float4 slot)
    reinterpret_cast<float4*>(
        g_partC + ((size_t)b * SPLIT + chunk) * H_)[tid] = acc;

    // combine warp-0 lane lsums
    if (warp == 0 && lane < TILE) lred[lane] = lsum;
    __syncthreads();
    if (tid == 0) {
        float l = 0.f;
        #pragma unroll
        for (int i = 0; i < TILE; i++) l += lred[i];
        g_partL[b * SPLIT + chunk] = l;
    }
}

// ---------------------------------------------------------------------------
// Pass 2 (merged): per-batch combine of SPLIT partials -> context [B,H],
// then weights[b,:] = expE[b,:] / l  (same block, no extra launch).
// ---------------------------------------------------------------------------
__global__ __launch_bounds__(THREADS)
void pass2_kernel(float* __restrict__ ctx_out, float* __restrict__ wts_out)
{
    const int b   = blockIdx.x;
    const int tid = threadIdx.x;
    __shared__ float s_inv;

    if (tid < 32) {
        float l = 0.f;
        for (int c = tid; c < SPLIT; c += 32)
            l += g_partL[b * SPLIT + c];
        #pragma unroll
        for (int off = 16; off; off >>= 1)
            l += __shfl_xor_sync(0xffffffffu, l, off);
        if (tid == 0) s_inv = 1.f / l;
    }
    __syncthreads();
    const float inv = s_inv;

    // context
    float4 acc = make_float4(0.f, 0.f, 0.f, 0.f);
    #pragma unroll
    for (int c = 0; c < SPLIT; c++) {
        float4 v = reinterpret_cast<const float4*>(
            g_partC + ((size_t)b * SPLIT + c) * H_)[tid];
        acc.x += v.x; acc.y += v.y; acc.z += v.z; acc.w += v.w;
    }
    acc.x *= inv; acc.y *= inv; acc.z *= inv; acc.w *= inv;
    reinterpret_cast<float4*>(ctx_out + (size_t)b * H_)[tid] = acc;

    // weights: S_/4 = 512 float4 per batch, 256 threads -> 2 iters
    #pragma unroll
    for (int i = 0; i < S_ / 4 / THREADS; i++) {
        const int idx = b * (S_ / 4) + i * THREADS + tid;
        float4 e = reinterpret_cast<const float4*>(g_expE)[idx];
        e.x *= inv; e.y *= inv; e.z *= inv; e.w *= inv;
        reinterpret_cast<float4*>(wts_out)[idx] = e;
    }
}

extern "C" void kernel_launch(void* const* d_in, const int* in_sizes, int n_in,
                              void* d_out, int out_size)
{
    const float* x    = (const float*)d_in[0];   // rnn_output [B,S,H]
    const float* w    = (const float*)d_in[1];   // attn_w [H]
    const float* bptr = (const float*)d_in[2];   // attn_b scalar

    float* out = (float*)d_out;                  // context [B,H] then weights [B,S]
    float* ctx_out = out;
    float* wts_out = out + (size_t)B_ * H_;

    pass1_kernel<<<B_ * SPLIT, THREADS>>>(x, w, bptr);
    pass2_kernel<<<B_, THREADS>>>(ctx_out, wts_out);
}